// round 2
// baseline (speedup 1.0000x reference)
#include <cuda_runtime.h>
#include <math.h>

#define Nn 64
#define Cc 256
#define Tt 64
#define Vv 25
#define Kk 8
#define VNh 5
#define VT 30
#define CG 32
#define HH 8
#define OO 256
#define OG 32
#define TOPK 9

// tiling for k_main
#define TB 16                  // t-tile
#define NROWS (CG * TB)        // 512 rows per block
#define XST 33                 // X row stride (conflict-free scalar reads)
#define BST 28                 // B row stride (u padded 25->28, float4-friendly)

// smem float offsets for k_main
#define AT_OFF 0               // A_T[v][u] : 30 x 28 = 840
#define RA_OFF 840             // rowsA[28]
#define WD_OFF 872             // Wd[c][o][{w0,w0,w1,w1}] : 32*16*4 = 2048
#define XB_OFF 2920            // X tile 512 x 33 = 16896 (B tile 512 x 28 in-place)
#define SM_TOTAL_FLOATS (XB_OFF + NROWS * XST)   // 19816 floats = 79264 B

// ---------------- device scratch ----------------
__device__ float g_pooled[Nn * Cc * VT];
__device__ float g_adjn[Kk * VT * VT];
__device__ float g_adj[Nn * Kk * VT * VT];

// ---------------- f32x2 helpers ----------------
__device__ __forceinline__ unsigned long long pack2(float lo, float hi) {
    unsigned long long r;
    asm("mov.b64 %0, {%1, %2};" : "=l"(r) : "f"(lo), "f"(hi));
    return r;
}
__device__ __forceinline__ void unpack2(unsigned long long v, float& lo, float& hi) {
    asm("mov.b64 {%0, %1}, %2;" : "=f"(lo), "=f"(hi) : "l"(v));
}
__device__ __forceinline__ void fma2(unsigned long long& acc, unsigned long long a,
                                     unsigned long long b) {
    asm("fma.rn.f32x2 %0, %1, %2, %0;" : "+l"(acc) : "l"(a), "l"(b));
}

// ---------------- kernel 0: normalized adjacency ----------------
__global__ void k_adjn(const float* __restrict__ adjc, const float* __restrict__ ei) {
    int r = threadIdx.x;
    if (r < Kk * VT) {
        int base = r * VT;
        float row[VT];
        float s = 0.f;
#pragma unroll
        for (int w = 0; w < VT; w++) {
            float v = ei[base + w] * adjc[base + w];
            row[w] = v;
            s += fabsf(v);
        }
        float inv = 1.f / (s + 1e-8f);
#pragma unroll
        for (int w = 0; w < VT; w++) g_adjn[base + w] = row[w] * inv;
    }
}

// ---------------- kernel 1: pooled = mean_t(xv), coalesced ----------------
__global__ __launch_bounds__(256) void k_pool(const float* __restrict__ x,
                                              const float* __restrict__ hj) {
    __shared__ float sp[4 * Tt * Vv];  // 6400 floats
    int n = blockIdx.x >> 6;
    int c0 = (blockIdx.x & 63) * 4;
    int tid = threadIdx.x;

    const float4* gx = (const float4*)(x + (size_t)(n * Cc + c0) * (Tt * Vv));
    float4* sp4 = (float4*)sp;
    for (int e = tid; e < 4 * Tt * Vv / 4; e += 256) sp4[e] = gx[e];
    __syncthreads();

    if (tid < 4 * Vv) {
        int c = tid / Vv, v = tid % Vv;
        float s = 0.f;
        const float* p = sp + c * (Tt * Vv) + v;
#pragma unroll 8
        for (int t = 0; t < Tt; t++) s += p[t * Vv];
        g_pooled[(n * Cc + c0 + c) * VT + v] = s * (1.f / (float)Tt);
    } else if (tid < 4 * Vv + 4 * VNh) {
        int e = tid - 4 * Vv;
        int c = e / VNh, j = e % VNh;
        g_pooled[(n * Cc + c0 + c) * VT + Vv + j] = hj[j * Cc + c0 + c];
    }
}

// ---------------- kernel 2: per-sample hypergraph adjacency ----------------
__global__ __launch_bounds__(256) void k_hyper(
    const float* __restrict__ tvw, const float* __restrict__ tvb,
    const float* __restrict__ t1w, const float* __restrict__ t1b,
    const float* __restrict__ t2w, const float* __restrict__ t2b,
    const float* __restrict__ alpha) {
    __shared__ float buf[Cc * VT];
    __shared__ float vproj[Kk * VT * HH];
    __shared__ float w1s[Kk * HH * VT];
    __shared__ float wt[Kk * VT];
    __shared__ float dv[Kk * VT];
    __shared__ float rs[Kk * VT];

    int n = blockIdx.x;
    int tid = threadIdx.x;

    for (int e = tid; e < Cc * VT; e += 256) buf[e] = g_pooled[n * Cc * VT + e];
    __syncthreads();

    for (int e = tid; e < 2 * Kk * VT * HH; e += 256) {
        if (e < Kk * VT * HH) {
            int k = e / (VT * HH);
            int v = (e / HH) % VT;
            int h = e % HH;
            float acc = tvb[k * HH + h];
            const float* w = tvw + (k * HH + h) * CG;
            const float* p = buf + (k * CG) * VT + v;
#pragma unroll 8
            for (int c = 0; c < CG; c++) acc += p[c * VT] * w[c];
            vproj[k * (VT * HH) + v * HH + h] = acc;
        } else {
            int e2 = e - Kk * VT * HH;
            int q = e2 / VT;
            int v = e2 % VT;
            int k = q / HH;
            float acc = t1b[q];
            const float* w = t1w + q * CG;
            const float* p = buf + (k * CG) * VT + v;
#pragma unroll 8
            for (int c = 0; c < CG; c++) acc += p[c * VT] * w[c];
            w1s[q * VT + v] = (acc >= 0.f) ? acc : 0.01f * acc;
        }
    }
    __syncthreads();

    float* incid = buf;
    for (int e = tid; e < Kk * VT * VT; e += 256) incid[e] = 0.f;
    if (tid < Kk * VT) {
        int k = tid / VT, v = tid % VT;
        float acc = t2b[k];
        const float* w = t2w + k * (Kk * HH);
#pragma unroll 8
        for (int q = 0; q < Kk * HH; q++) acc += w1s[q * VT + v] * w[q];
        wt[tid] = tanhf(acc);
    }
    __syncthreads();

    if (tid < Kk * VT) {
        int k = tid / VT, u = tid % VT;
        float vu[HH];
#pragma unroll
        for (int h = 0; h < HH; h++) vu[h] = vproj[k * (VT * HH) + u * HH + h];
        float nd[VT];
#pragma unroll
        for (int w = 0; w < VT; w++) {
            float d2 = 0.f;
#pragma unroll
            for (int h = 0; h < HH; h++) {
                float df = vu[h] - vproj[k * (VT * HH) + w * HH + h];
                d2 += df * df;
            }
            nd[w] = (d2 > 0.f) ? -sqrtf(d2) : 0.f;
        }
        float vals[TOPK];
        int ids[TOPK];
        unsigned used = 0u;
#pragma unroll
        for (int j = 0; j < TOPK; j++) {
            float best = -INFINITY;
            int bi = 0;
#pragma unroll
            for (int w = 0; w < VT; w++) {
                bool free_w = ((used >> w) & 1u) == 0u;
                if (free_w && nd[w] > best) { best = nd[w]; bi = w; }
            }
            vals[j] = best;
            ids[j] = bi;
            used |= (1u << bi);
        }
        float m = vals[0];
        float pr[TOPK];
        float se = 0.f;
#pragma unroll
        for (int j = 0; j < TOPK; j++) { pr[j] = expf(vals[j] - m); se += pr[j]; }
        float inv = 1.f / se;
#pragma unroll
        for (int j = 0; j < TOPK; j++) incid[k * (VT * VT) + u * VT + ids[j]] = pr[j] * inv;
    }
    __syncthreads();

    if (tid < 2 * Kk * VT) {
        if (tid < Kk * VT) {
            int k = tid / VT, v = tid % VT;
            float s = 0.f;
#pragma unroll 6
            for (int u = 0; u < VT; u++) s += fabsf(incid[k * (VT * VT) + u * VT + v]);
            dv[tid] = wt[tid] / (s + 1e-8f);
        } else {
            int e = tid - Kk * VT;
            int k = e / VT, u = e % VT;
            float s = 0.f;
#pragma unroll 6
            for (int v = 0; v < VT; v++)
                s += fabsf(incid[k * (VT * VT) + u * VT + v] * wt[k * VT + v]);
            rs[e] = s + 1e-8f;
        }
    }
    __syncthreads();

    float ra = fmaxf(alpha[0], 0.f);
    for (int e = tid; e < Kk * VT * VT; e += 256) {
        int k = e / (VT * VT);
        int u = (e / VT) % VT;
        int w = e % VT;
        const float* ru = incid + k * (VT * VT) + u * VT;
        const float* rw = incid + k * (VT * VT) + w * VT;
        const float* dk = dv + k * VT;
        const float* wk = wt + k * VT;
        float ha = 0.f;
#pragma unroll 6
        for (int v = 0; v < VT; v++) ha += ru[v] * wk[v] * dk[v] * rw[v];
        ha /= rs[k * VT + u];
        g_adj[n * (Kk * VT * VT) + e] = g_adjn[e] + ra * ha;
    }
}

// ---------------- kernel 3: fused conv + aggregate + BN + relu (f32x2) ----------------
__global__ __launch_bounds__(256, 2) void k_main(
    const float* __restrict__ x, const float* __restrict__ hj,
    const float* __restrict__ cdw, const float* __restrict__ cdb,
    const float* __restrict__ gam, const float* __restrict__ bet,
    float* __restrict__ out) {
    extern __shared__ float sm[];
    float* At = sm + AT_OFF;      // A_T[v*28 + u], u padded 25->28 with zeros
    float* rowsA = sm + RA_OFF;   // rowsA[28]
    float* Wd = sm + WD_OFF;      // Wd[(c*16+o)*4 + {w0,w0,w1,w1}]
    float* XB = sm + XB_OFF;      // X [512 x 33] then (in-place) B [512 x 28]

    int bid = blockIdx.x;
    int tb = bid & 3;             // t-tile (Tt/TB = 4)
    int k = (bid >> 2) & 7;
    int n = bid >> 5;
    int tid = threadIdx.x;

    // --- fill A_T (transposed, zero-padded to 28 u) ---
    const float* gA = g_adj + (n * Kk + k) * (VT * VT);
    for (int e = tid; e < VT * BST; e += 256) {
        int v = e / BST, u = e - v * BST;
        At[e] = (u < Vv) ? gA[u * VT + v] : 0.f;
    }
    // --- rowsA ---
    if (tid < BST) {
        float s = 0.f;
        if (tid < Vv) {
#pragma unroll
            for (int v = 0; v < VT; v++) s += gA[tid * VT + v];
        }
        rowsA[tid] = s;
    }
    // --- fill Wd (duplicated pairs for f32x2) ---
    for (int e = tid; e < CG * 16 * 4; e += 256) {
        int c = e >> 6;
        int r = e & 63;
        int o = r >> 2;
        int sel = (r >> 1) & 1;
        Wd[e] = cdw[(k * OG + o + 16 * sel) * CG + c];
    }
    // --- fill X tile [row = c*TB+tt][v], stride 33 ---
    {
        const float* gx = x + ((size_t)(n * Cc + k * CG) * Tt + tb * TB) * Vv;
        for (int e = tid; e < CG * TB * Vv; e += 256) {
            int c = e / (TB * Vv);
            int r = e - c * (TB * Vv);
            int tt = r / Vv;
            int v = r - tt * Vv;
            XB[(c * TB + tt) * XST + v] = gx[(size_t)c * (Tt * Vv) + r];
        }
        for (int e = tid; e < CG * TB * VNh; e += 256) {
            int c = e / (TB * VNh);
            int r = e - c * (TB * VNh);
            int tt = r / VNh;
            int j = r - tt * VNh;
            XB[(c * TB + tt) * XST + Vv + j] = hj[j * Cc + k * CG + c];
        }
    }
    __syncthreads();

    // --- stage B: B[r][u] = sum_v A[u][v] * X[r][v]; 2 rows/thread; acc packed over u ---
    unsigned long long acc0[14], acc1[14];
#pragma unroll
    for (int i = 0; i < 14; i++) { acc0[i] = 0ull; acc1[i] = 0ull; }
    {
        const float* x0 = XB + tid * XST;
        const float* x1 = XB + (tid + 256) * XST;
#pragma unroll 1
        for (int v = 0; v < VT; v++) {
            float xa = x0[v], xb = x1[v];
            unsigned long long xd0 = pack2(xa, xa);
            unsigned long long xd1 = pack2(xb, xb);
            const ulonglong2* arow = (const ulonglong2*)(At + v * BST);
#pragma unroll
            for (int u4 = 0; u4 < 7; u4++) {
                ulonglong2 ap = arow[u4];
                fma2(acc0[2 * u4], ap.x, xd0);
                fma2(acc0[2 * u4 + 1], ap.y, xd0);
                fma2(acc1[2 * u4], ap.x, xd1);
                fma2(acc1[2 * u4 + 1], ap.y, xd1);
            }
        }
    }
    __syncthreads();   // all X reads done -> safe to overwrite region with B
    {
        ulonglong2* b0 = (ulonglong2*)(XB + tid * BST);
        ulonglong2* b1 = (ulonglong2*)(XB + (tid + 256) * BST);
#pragma unroll
        for (int u4 = 0; u4 < 7; u4++) {
            ulonglong2 s0, s1;
            s0.x = acc0[2 * u4]; s0.y = acc0[2 * u4 + 1];
            s1.x = acc1[2 * u4]; s1.y = acc1[2 * u4 + 1];
            b0[u4] = s0;
            b1[u4] = s1;
        }
    }
    __syncthreads();

    // --- stage C: Y[o][t][u] = b[o]*rowsA[u] + sum_c W[o][c]*B[c*TB+tt][u] ---
    {
        int ttl = tid & 15;
        int o = tid >> 4;                 // 0..15, handles o and o+16
        float bt0 = cdb[k * OG + o];
        float bt1 = cdb[k * OG + o + 16];
        unsigned long long acc[2][14];
#pragma unroll
        for (int u2 = 0; u2 < 14; u2++) {
            float r0 = rowsA[2 * u2], r1 = rowsA[2 * u2 + 1];
            acc[0][u2] = pack2(bt0 * r0, bt0 * r1);
            acc[1][u2] = pack2(bt1 * r0, bt1 * r1);
        }
#pragma unroll 1
        for (int c = 0; c < CG; c++) {
            unsigned long long w0 = *(const unsigned long long*)(Wd + (c * 16 + o) * 4);
            unsigned long long w1 = *(const unsigned long long*)(Wd + (c * 16 + o) * 4 + 2);
            const ulonglong2* bp = (const ulonglong2*)(XB + (c * TB + ttl) * BST);
#pragma unroll
            for (int u4 = 0; u4 < 7; u4++) {
                ulonglong2 bv = bp[u4];
                fma2(acc[0][2 * u4], w0, bv.x);
                fma2(acc[0][2 * u4 + 1], w0, bv.y);
                fma2(acc[1][2 * u4], w1, bv.x);
                fma2(acc[1][2 * u4 + 1], w1, bv.y);
            }
        }
        int t = tb * TB + ttl;
#pragma unroll
        for (int sel = 0; sel < 2; sel++) {
            int oo = k * OG + o + 16 * sel;
            float scale = gam[oo] / sqrtf(1.0f + 1e-5f);
            float bb = bet[oo];
            size_t base = ((size_t)(n * Cc + oo) * Tt + t) * Vv;
            float y[26];
#pragma unroll
            for (int u2 = 0; u2 < 13; u2++) unpack2(acc[sel][u2], y[2 * u2], y[2 * u2 + 1]);
#pragma unroll
            for (int u = 0; u < Vv; u++) {
                float val = y[u] * scale + bb + x[base + u];
                out[base + u] = fmaxf(val, 0.f);
            }
        }
    }
}

// ---------------- kernel 4: copy hyper_joint into output tail ----------------
__global__ void k_tail(const float* __restrict__ hj, float* __restrict__ out, int tail) {
    int i = blockIdx.x * blockDim.x + threadIdx.x;
    if (i < tail && i < VNh * Cc) out[(size_t)Nn * OO * Tt * Vv + i] = hj[i];
}

// ---------------- launch ----------------
extern "C" void kernel_launch(void* const* d_in, const int* in_sizes, int n_in,
                              void* d_out, int out_size) {
    const float* x    = (const float*)d_in[0];
    const float* adjc = (const float*)d_in[1];
    const float* ei   = (const float*)d_in[2];
    const float* hj   = (const float*)d_in[3];
    const float* alp  = (const float*)d_in[4];
    const float* tvw  = (const float*)d_in[5];
    const float* tvb  = (const float*)d_in[6];
    const float* t1w  = (const float*)d_in[7];
    const float* t1b  = (const float*)d_in[8];
    const float* t2w  = (const float*)d_in[9];
    const float* t2b  = (const float*)d_in[10];
    const float* cdw  = (const float*)d_in[11];
    const float* cdb  = (const float*)d_in[12];
    const float* gam  = (const float*)d_in[13];
    const float* bet  = (const float*)d_in[14];
    float* out = (float*)d_out;

    k_adjn<<<1, 256>>>(adjc, ei);
    k_pool<<<Nn * (Cc / 4), 256>>>(x, hj);
    k_hyper<<<Nn, 256>>>(tvw, tvb, t1w, t1b, t2w, t2b, alp);

    cudaFuncSetAttribute(k_main, cudaFuncAttributeMaxDynamicSharedMemorySize,
                         SM_TOTAL_FLOATS * 4);
    k_main<<<Nn * Kk * (Tt / TB), 256, SM_TOTAL_FLOATS * 4>>>(x, hj, cdw, cdb, gam, bet, out);

    int tail = out_size - Nn * OO * Tt * Vv;
    if (tail > 0) {
        k_tail<<<(tail + 255) / 256, 256>>>(hj, out, tail);
    }
}

// round 3
// speedup vs baseline: 1.1254x; 1.1254x over previous
#include <cuda_runtime.h>
#include <math.h>

#define Nn 64
#define Cc 256
#define Tt 64
#define Vv 25
#define Kk 8
#define VNh 5
#define VT 30
#define CG 32
#define HH 8
#define OO 256
#define OG 32
#define TOPK 9

// tiling for k_main
#define TB 8                   // t-tile
#define NROWS (CG * TB)        // 256 rows per block
#define XST 33                 // X row stride (conflict-free scalar reads)
#define BST 28                 // B row stride (u padded 25->28)

// smem float offsets for k_main
#define AT_OFF 0               // A_T[v][u] : 30 x 28 = 840
#define RA_OFF 840             // rowsA[28]
#define WS_OFF 868             // Ws[o*33+c] : 32*33 = 1056
#define XB_OFF 1924            // X tile 256 x 33 = 8448 (B 256 x 28 in-place)
#define SM_TOTAL_FLOATS (XB_OFF + NROWS * XST)   // 10372 floats = 41488 B

// ---------------- device scratch ----------------
__device__ float g_pooled[Nn * Cc * VT];
__device__ float g_adjn[Kk * VT * VT];
__device__ float g_adj[Nn * Kk * VT * VT];
__device__ float g_vproj[Nn * Kk * VT * HH];
__device__ float g_w1[Nn * Kk * HH * VT];

// ---------------- f32x2 helpers ----------------
__device__ __forceinline__ unsigned long long pack2(float lo, float hi) {
    unsigned long long r;
    asm("mov.b64 %0, {%1, %2};" : "=l"(r) : "f"(lo), "f"(hi));
    return r;
}
__device__ __forceinline__ void unpack2(unsigned long long v, float& lo, float& hi) {
    asm("mov.b64 {%0, %1}, %2;" : "=f"(lo), "=f"(hi) : "l"(v));
}
__device__ __forceinline__ void fma2(unsigned long long& acc, unsigned long long a,
                                     unsigned long long b) {
    asm("fma.rn.f32x2 %0, %1, %2, %0;" : "+l"(acc) : "l"(a), "l"(b));
}

// ---------------- kernel 0: normalized adjacency + output tail ----------------
__global__ void k_adjn(const float* __restrict__ adjc, const float* __restrict__ ei,
                       const float* __restrict__ hj, float* __restrict__ out, int tail) {
    int r = threadIdx.x;
    if (r < Kk * VT) {
        int base = r * VT;
        float row[VT];
        float s = 0.f;
#pragma unroll
        for (int w = 0; w < VT; w++) {
            float v = ei[base + w] * adjc[base + w];
            row[w] = v;
            s += fabsf(v);
        }
        float inv = 1.f / (s + 1e-8f);
#pragma unroll
        for (int w = 0; w < VT; w++) g_adjn[base + w] = row[w] * inv;
    }
    // hyper_joint tail of the output
    for (int i = r; i < tail && i < VNh * Cc; i += 256)
        out[(size_t)Nn * OO * Tt * Vv + i] = hj[i];
}

// ---------------- kernel 1: pooled = mean_t(xv), coalesced ----------------
__global__ __launch_bounds__(256) void k_pool(const float* __restrict__ x,
                                              const float* __restrict__ hj) {
    __shared__ float sp[4 * Tt * Vv];
    int n = blockIdx.x >> 6;
    int c0 = (blockIdx.x & 63) * 4;
    int tid = threadIdx.x;

    const float4* gx = (const float4*)(x + (size_t)(n * Cc + c0) * (Tt * Vv));
    float4* sp4 = (float4*)sp;
    for (int e = tid; e < 4 * Tt * Vv / 4; e += 256) sp4[e] = gx[e];
    __syncthreads();

    if (tid < 4 * Vv) {
        int c = tid / Vv, v = tid % Vv;
        float s = 0.f;
        const float* p = sp + c * (Tt * Vv) + v;
#pragma unroll 8
        for (int t = 0; t < Tt; t++) s += p[t * Vv];
        g_pooled[(n * Cc + c0 + c) * VT + v] = s * (1.f / (float)Tt);
    } else if (tid < 4 * Vv + 4 * VNh) {
        int e = tid - 4 * Vv;
        int c = e / VNh, j = e % VNh;
        g_pooled[(n * Cc + c0 + c) * VT + Vv + j] = hj[j * Cc + c0 + c];
    }
}

// ---------------- kernel 2a: vproj + w1 per (n,k) ----------------
__global__ __launch_bounds__(128) void k_hA(
    const float* __restrict__ tvw, const float* __restrict__ tvb,
    const float* __restrict__ t1w, const float* __restrict__ t1b) {
    __shared__ float ps[CG * VT];   // pooled slice [c][v]
    int n = blockIdx.x >> 3;
    int k = blockIdx.x & 7;
    int tid = threadIdx.x;

    for (int e = tid; e < CG * VT; e += 128)
        ps[e] = g_pooled[(n * Cc + k * CG) * VT + e];
    __syncthreads();

    for (int e = tid; e < 2 * VT * HH; e += 128) {
        if (e < VT * HH) {
            int v = e >> 3, h = e & 7;
            float acc = tvb[k * HH + h];
            const float* w = tvw + (k * HH + h) * CG;
#pragma unroll 8
            for (int c = 0; c < CG; c++) acc += ps[c * VT + v] * w[c];
            g_vproj[((n * Kk + k) * VT + v) * HH + h] = acc;
        } else {
            int e2 = e - VT * HH;
            int h = e2 / VT, v = e2 % VT;
            float acc = t1b[k * HH + h];
            const float* w = t1w + (k * HH + h) * CG;
#pragma unroll 8
            for (int c = 0; c < CG; c++) acc += ps[c * VT + v] * w[c];
            g_w1[(n * (Kk * HH) + k * HH + h) * VT + v] =
                (acc >= 0.f) ? acc : 0.01f * acc;
        }
    }
}

// ---------------- kernel 2b: weights/topk/incidence -> adj_full per (n,k) ----------------
__global__ __launch_bounds__(128) void k_hB(
    const float* __restrict__ t2w, const float* __restrict__ t2b,
    const float* __restrict__ alpha) {
    __shared__ float w1a[Kk * HH * VT];   // 1920
    __shared__ float vp[VT * HH];         // 240
    __shared__ float t2[Kk * HH];         // 64
    __shared__ float incid[VT * VT];      // 900
    __shared__ float tmp[VT * VT];        // 900: incid*wt*dv
    __shared__ float wt[VT], dvv[VT], rss[VT];

    int n = blockIdx.x >> 3;
    int k = blockIdx.x & 7;
    int tid = threadIdx.x;

    for (int e = tid; e < Kk * HH * VT; e += 128) w1a[e] = g_w1[n * (Kk * HH * VT) + e];
    for (int e = tid; e < VT * HH; e += 128) vp[e] = g_vproj[(n * Kk + k) * (VT * HH) + e];
    if (tid < Kk * HH) t2[tid] = t2w[k * (Kk * HH) + tid];
    for (int e = tid; e < VT * VT; e += 128) incid[e] = 0.f;
    __syncthreads();

    if (tid < VT) {
        float acc = t2b[k];
#pragma unroll 8
        for (int q = 0; q < Kk * HH; q++) acc += w1a[q * VT + tid] * t2[q];
        wt[tid] = tanhf(acc);
    }
    __syncthreads();

    if (tid < VT) {
        int u = tid;
        float vu[HH];
#pragma unroll
        for (int h = 0; h < HH; h++) vu[h] = vp[u * HH + h];
        float nd[VT];
#pragma unroll
        for (int w = 0; w < VT; w++) {
            float d2 = 0.f;
#pragma unroll
            for (int h = 0; h < HH; h++) {
                float df = vu[h] - vp[w * HH + h];
                d2 += df * df;
            }
            nd[w] = (d2 > 0.f) ? -sqrtf(d2) : 0.f;
        }
        float vals[TOPK];
        int ids[TOPK];
        unsigned used = 0u;
#pragma unroll
        for (int j = 0; j < TOPK; j++) {
            float best = -INFINITY;
            int bi = 0;
#pragma unroll
            for (int w = 0; w < VT; w++) {
                bool free_w = ((used >> w) & 1u) == 0u;
                if (free_w && nd[w] > best) { best = nd[w]; bi = w; }
            }
            vals[j] = best;
            ids[j] = bi;
            used |= (1u << bi);
        }
        float m = vals[0];
        float pr[TOPK];
        float se = 0.f;
#pragma unroll
        for (int j = 0; j < TOPK; j++) { pr[j] = expf(vals[j] - m); se += pr[j]; }
        float inv = 1.f / se;
#pragma unroll
        for (int j = 0; j < TOPK; j++) incid[u * VT + ids[j]] = pr[j] * inv;
    }
    __syncthreads();

    if (tid < 2 * VT) {
        if (tid < VT) {  // column sums -> dvv
            float s = 0.f;
#pragma unroll 6
            for (int u = 0; u < VT; u++) s += fabsf(incid[u * VT + tid]);
            dvv[tid] = wt[tid] / (s + 1e-8f);
        } else {        // row sums of inc_w -> rss
            int u = tid - VT;
            float s = 0.f;
#pragma unroll 6
            for (int v = 0; v < VT; v++) s += fabsf(incid[u * VT + v] * wt[v]);
            rss[u] = s + 1e-8f;
        }
    }
    __syncthreads();
    for (int e = tid; e < VT * VT; e += 128) tmp[e] = incid[e] * wt[e % VT] * dvv[e % VT];
    __syncthreads();

    float ra = fmaxf(alpha[0], 0.f);
    for (int e = tid; e < VT * VT; e += 128) {
        int u = e / VT, w = e % VT;
        const float* ru = tmp + u * VT;
        const float* rw = incid + w * VT;
        float ha = 0.f;
#pragma unroll 6
        for (int v = 0; v < VT; v++) ha += ru[v] * rw[v];
        ha /= rss[u];
        g_adj[(n * Kk + k) * (VT * VT) + e] = g_adjn[k * (VT * VT) + e] + ra * ha;
    }
}

// ---------------- kernel 3: fused conv + aggregate + BN + relu (f32x2, hi-occ) ----------------
__global__ __launch_bounds__(256, 4) void k_main(
    const float* __restrict__ x, const float* __restrict__ hj,
    const float* __restrict__ cdw, const float* __restrict__ cdb,
    const float* __restrict__ gam, const float* __restrict__ bet,
    float* __restrict__ out) {
    extern __shared__ float sm[];
    float* At = sm + AT_OFF;      // A_T[v*28 + u]
    float* rowsA = sm + RA_OFF;
    float* Ws = sm + WS_OFF;      // [o*33 + c]
    float* XB = sm + XB_OFF;      // X [256 x 33] then (in-place) B [256 x 28]

    int bid = blockIdx.x;
    int tb = bid & 7;             // Tt/TB = 8 tiles
    int k = (bid >> 3) & 7;
    int n = bid >> 6;
    int tid = threadIdx.x;

    // --- A_T (zero-padded u 25->28) ---
    const float* gA = g_adj + (n * Kk + k) * (VT * VT);
    for (int e = tid; e < VT * BST; e += 256) {
        int v = e / BST, u = e - v * BST;
        At[e] = (u < Vv) ? gA[u * VT + v] : 0.f;
    }
    if (tid < BST) {
        float s = 0.f;
        if (tid < Vv) {
#pragma unroll
            for (int v = 0; v < VT; v++) s += gA[tid * VT + v];
        }
        rowsA[tid] = s;
    }
    // --- weights [o][c], stride 33 ---
    for (int e = tid; e < CG * CG; e += 256) {
        int o = e >> 5, c = e & 31;
        Ws[o * 33 + c] = cdw[(k * OG + o) * CG + c];
    }
    // --- X tile [row=c*TB+tt][v], stride 33 ---
    {
        const float* gx = x + ((size_t)(n * Cc + k * CG) * Tt + tb * TB) * Vv;
        for (int e = tid; e < CG * TB * Vv; e += 256) {
            int c = e / (TB * Vv);
            int r = e - c * (TB * Vv);
            int tt = r / Vv;
            int v = r - tt * Vv;
            XB[(c * TB + tt) * XST + v] = gx[(size_t)c * (Tt * Vv) + r];
        }
        for (int e = tid; e < CG * TB * VNh; e += 256) {
            int c = e / (TB * VNh);
            int r = e - c * (TB * VNh);
            int tt = r / VNh;
            int j = r - tt * VNh;
            XB[(c * TB + tt) * XST + Vv + j] = hj[j * Cc + k * CG + c];
        }
    }
    __syncthreads();

    // --- stage B: B[r][u] = sum_v A[u][v]*X[r][v]; one row per thread ---
    unsigned long long acc[14];
#pragma unroll
    for (int i = 0; i < 14; i++) acc[i] = 0ull;
    {
        const float* x0 = XB + tid * XST;
#pragma unroll 3
        for (int v = 0; v < VT; v++) {
            float xa = x0[v];
            unsigned long long xd = pack2(xa, xa);
            const ulonglong2* arow = (const ulonglong2*)(At + v * BST);
#pragma unroll
            for (int u4 = 0; u4 < 7; u4++) {
                ulonglong2 ap = arow[u4];
                fma2(acc[2 * u4], ap.x, xd);
                fma2(acc[2 * u4 + 1], ap.y, xd);
            }
        }
    }
    __syncthreads();   // all X reads complete
    {
        ulonglong2* b0 = (ulonglong2*)(XB + tid * BST);
#pragma unroll
        for (int u4 = 0; u4 < 7; u4++) {
            ulonglong2 s0;
            s0.x = acc[2 * u4];
            s0.y = acc[2 * u4 + 1];
            b0[u4] = s0;
        }
    }
    __syncthreads();

    // --- stage C: one (o, tt) per thread ---
    {
        int ttl = tid & 7;
        int o = tid >> 3;
        int oo = k * OG + o;
        float bt = cdb[oo];
#pragma unroll
        for (int u2 = 0; u2 < 14; u2++)
            acc[u2] = pack2(bt * rowsA[2 * u2], bt * rowsA[2 * u2 + 1]);
#pragma unroll 4
        for (int c = 0; c < CG; c++) {
            float w = Ws[o * 33 + c];
            unsigned long long wd = pack2(w, w);
            const ulonglong2* bp = (const ulonglong2*)(XB + (c * TB + ttl) * BST);
#pragma unroll
            for (int u4 = 0; u4 < 7; u4++) {
                ulonglong2 bv = bp[u4];
                fma2(acc[2 * u4], wd, bv.x);
                fma2(acc[2 * u4 + 1], wd, bv.y);
            }
        }
        float scale = gam[oo] / sqrtf(1.0f + 1e-5f);
        float bb = bet[oo];
        int t = tb * TB + ttl;
        size_t base = ((size_t)(n * Cc + oo) * Tt + t) * Vv;
        float y[26];
#pragma unroll
        for (int u2 = 0; u2 < 13; u2++) unpack2(acc[u2], y[2 * u2], y[2 * u2 + 1]);
#pragma unroll
        for (int u = 0; u < Vv; u++) {
            float val = y[u] * scale + bb + x[base + u];
            out[base + u] = fmaxf(val, 0.f);
        }
    }
}

// ---------------- launch ----------------
extern "C" void kernel_launch(void* const* d_in, const int* in_sizes, int n_in,
                              void* d_out, int out_size) {
    const float* x    = (const float*)d_in[0];
    const float* adjc = (const float*)d_in[1];
    const float* ei   = (const float*)d_in[2];
    const float* hj   = (const float*)d_in[3];
    const float* alp  = (const float*)d_in[4];
    const float* tvw  = (const float*)d_in[5];
    const float* tvb  = (const float*)d_in[6];
    const float* t1w  = (const float*)d_in[7];
    const float* t1b  = (const float*)d_in[8];
    const float* t2w  = (const float*)d_in[9];
    const float* t2b  = (const float*)d_in[10];
    const float* cdw  = (const float*)d_in[11];
    const float* cdb  = (const float*)d_in[12];
    const float* gam  = (const float*)d_in[13];
    const float* bet  = (const float*)d_in[14];
    float* out = (float*)d_out;

    int tail = out_size - Nn * OO * Tt * Vv;
    k_adjn<<<1, 256>>>(adjc, ei, hj, out, tail);
    k_pool<<<Nn * (Cc / 4), 256>>>(x, hj);
    k_hA<<<Nn * Kk, 128>>>(tvw, tvb, t1w, t1b);
    k_hB<<<Nn * Kk, 128>>>(t2w, t2b, alp);

    cudaFuncSetAttribute(k_main, cudaFuncAttributeMaxDynamicSharedMemorySize,
                         SM_TOTAL_FLOATS * 4);
    k_main<<<Nn * Kk * (Tt / TB), 256, SM_TOTAL_FLOATS * 4>>>(x, hj, cdw, cdb, gam, bet, out);
}

// round 4
// speedup vs baseline: 1.5094x; 1.3412x over previous
#include <cuda_runtime.h>
#include <math.h>

#define Nn 64
#define Cc 256
#define Tt 64
#define Vv 25
#define Kk 8
#define VNh 5
#define VT 30
#define CG 32
#define HH 8
#define OO 256
#define OG 32
#define TOPK 9

// tiling for k_main
#define TB 8                   // t-tile
#define NROWS (CG * TB)        // 256 rows per block
#define XST 33                 // X row stride
#define BST 28                 // B row stride (u padded 25->28)

// smem float offsets for k_main
#define AT_OFF 0               // A_T[v][u] : 30 x 28 = 840
#define RA_OFF 840             // rowsA[28]
#define WS_OFF 868             // Ws[o*33+c] : 32*33 = 1056
#define XB_OFF 1924            // X tile 256x33 = 8448; then B 256x28; then Y 32x200
#define SM_TOTAL_FLOATS (XB_OFF + NROWS * XST)   // 10372 floats = 41488 B

// ---------------- device scratch ----------------
__device__ float g_pooled[Nn * Cc * VT];
__device__ float g_adjn[Kk * VT * VT];
__device__ float g_adj[Nn * Kk * VT * VT];
__device__ float g_vproj[Nn * Kk * VT * HH];
__device__ float g_w1[Nn * Kk * HH * VT];

// ---------------- f32x2 helpers ----------------
__device__ __forceinline__ unsigned long long pack2(float lo, float hi) {
    unsigned long long r;
    asm("mov.b64 %0, {%1, %2};" : "=l"(r) : "f"(lo), "f"(hi));
    return r;
}
__device__ __forceinline__ void unpack2(unsigned long long v, float& lo, float& hi) {
    asm("mov.b64 {%0, %1}, %2;" : "=f"(lo), "=f"(hi) : "l"(v));
}
__device__ __forceinline__ void fma2(unsigned long long& acc, unsigned long long a,
                                     unsigned long long b) {
    asm("fma.rn.f32x2 %0, %1, %2, %0;" : "+l"(acc) : "l"(a), "l"(b));
}

// ---------------- kernel 0: normalized adjacency + output tail ----------------
__global__ void k_adjn(const float* __restrict__ adjc, const float* __restrict__ ei,
                       const float* __restrict__ hj, float* __restrict__ out, int tail) {
    int r = threadIdx.x;
    if (r < Kk * VT) {
        int base = r * VT;
        float row[VT];
        float s = 0.f;
#pragma unroll
        for (int w = 0; w < VT; w++) {
            float v = ei[base + w] * adjc[base + w];
            row[w] = v;
            s += fabsf(v);
        }
        float inv = 1.f / (s + 1e-8f);
#pragma unroll
        for (int w = 0; w < VT; w++) g_adjn[base + w] = row[w] * inv;
    }
    for (int i = r; i < tail && i < VNh * Cc; i += 256)
        out[(size_t)Nn * OO * Tt * Vv + i] = hj[i];
}

// ---------------- kernel 1: pooled = mean_t(xv), coalesced ----------------
__global__ __launch_bounds__(256) void k_pool(const float* __restrict__ x,
                                              const float* __restrict__ hj) {
    __shared__ float sp[4 * Tt * Vv];
    int n = blockIdx.x >> 6;
    int c0 = (blockIdx.x & 63) * 4;
    int tid = threadIdx.x;

    const float4* gx = (const float4*)(x + (size_t)(n * Cc + c0) * (Tt * Vv));
    float4* sp4 = (float4*)sp;
    for (int e = tid; e < 4 * Tt * Vv / 4; e += 256) sp4[e] = gx[e];
    __syncthreads();

    if (tid < 4 * Vv) {
        int c = tid / Vv, v = tid % Vv;
        float s = 0.f;
        const float* p = sp + c * (Tt * Vv) + v;
#pragma unroll 8
        for (int t = 0; t < Tt; t++) s += p[t * Vv];
        g_pooled[(n * Cc + c0 + c) * VT + v] = s * (1.f / (float)Tt);
    } else if (tid < 4 * Vv + 4 * VNh) {
        int e = tid - 4 * Vv;
        int c = e / VNh, j = e % VNh;
        g_pooled[(n * Cc + c0 + c) * VT + Vv + j] = hj[j * Cc + c0 + c];
    }
}

// ---------------- kernel 2a: vproj + w1 per (n,k) ----------------
__global__ __launch_bounds__(128) void k_hA(
    const float* __restrict__ tvw, const float* __restrict__ tvb,
    const float* __restrict__ t1w, const float* __restrict__ t1b) {
    __shared__ float ps[CG * VT];
    int n = blockIdx.x >> 3;
    int k = blockIdx.x & 7;
    int tid = threadIdx.x;

    for (int e = tid; e < CG * VT; e += 128)
        ps[e] = g_pooled[(n * Cc + k * CG) * VT + e];
    __syncthreads();

    for (int e = tid; e < 2 * VT * HH; e += 128) {
        if (e < VT * HH) {
            int v = e >> 3, h = e & 7;
            float acc = tvb[k * HH + h];
            const float* w = tvw + (k * HH + h) * CG;
#pragma unroll 8
            for (int c = 0; c < CG; c++) acc += ps[c * VT + v] * w[c];
            g_vproj[((n * Kk + k) * VT + v) * HH + h] = acc;
        } else {
            int e2 = e - VT * HH;
            int h = e2 / VT, v = e2 % VT;
            float acc = t1b[k * HH + h];
            const float* w = t1w + (k * HH + h) * CG;
#pragma unroll 8
            for (int c = 0; c < CG; c++) acc += ps[c * VT + v] * w[c];
            g_w1[(n * (Kk * HH) + k * HH + h) * VT + v] =
                (acc >= 0.f) ? acc : 0.01f * acc;
        }
    }
}

// ---------------- kernel 2b: weights/topk/incidence -> adj_full per (n,k) ----------------
__global__ __launch_bounds__(128) void k_hB(
    const float* __restrict__ t2w, const float* __restrict__ t2b,
    const float* __restrict__ alpha) {
    __shared__ float w1a[Kk * HH * VT];   // 1920
    __shared__ float vp[VT * HH];         // 240
    __shared__ float t2[Kk * HH];         // 64
    __shared__ float nd[VT * 33];         // 990: -dist matrix, stride 33
    __shared__ float incid[VT * VT];      // 900
    __shared__ float tmp[VT * VT];        // 900
    __shared__ float wt[VT], dvv[VT], rss[VT];

    int n = blockIdx.x >> 3;
    int k = blockIdx.x & 7;
    int tid = threadIdx.x;

    for (int e = tid; e < Kk * HH * VT; e += 128) w1a[e] = g_w1[n * (Kk * HH * VT) + e];
    for (int e = tid; e < VT * HH; e += 128) vp[e] = g_vproj[(n * Kk + k) * (VT * HH) + e];
    if (tid < Kk * HH) t2[tid] = t2w[k * (Kk * HH) + tid];
    for (int e = tid; e < VT * VT; e += 128) incid[e] = 0.f;
    __syncthreads();

    // weights (30 threads) + distances (all 128 threads on 900 pairs)
    if (tid < VT) {
        float acc = t2b[k];
#pragma unroll 8
        for (int q = 0; q < Kk * HH; q++) acc += w1a[q * VT + tid] * t2[q];
        wt[tid] = tanhf(acc);
    }
    for (int e = tid; e < VT * VT; e += 128) {
        int u = e / VT, w = e % VT;
        float d2 = 0.f;
#pragma unroll
        for (int h = 0; h < HH; h++) {
            float df = vp[u * HH + h] - vp[w * HH + h];
            d2 += df * df;
        }
        nd[u * 33 + w] = (d2 > 0.f) ? -sqrtf(d2) : 0.f;
    }
    __syncthreads();

    // top-k + softmax per row u (30 threads)
    if (tid < VT) {
        int u = tid;
        float ndr[VT];
#pragma unroll
        for (int w = 0; w < VT; w++) ndr[w] = nd[u * 33 + w];
        float vals[TOPK];
        int ids[TOPK];
        unsigned used = 0u;
#pragma unroll
        for (int j = 0; j < TOPK; j++) {
            float best = -INFINITY;
            int bi = 0;
#pragma unroll
            for (int w = 0; w < VT; w++) {
                bool free_w = ((used >> w) & 1u) == 0u;
                if (free_w && ndr[w] > best) { best = ndr[w]; bi = w; }
            }
            vals[j] = best;
            ids[j] = bi;
            used |= (1u << bi);
        }
        float m = vals[0];
        float pr[TOPK];
        float se = 0.f;
#pragma unroll
        for (int j = 0; j < TOPK; j++) { pr[j] = expf(vals[j] - m); se += pr[j]; }
        float inv = 1.f / se;
#pragma unroll
        for (int j = 0; j < TOPK; j++) incid[u * VT + ids[j]] = pr[j] * inv;
    }
    __syncthreads();

    if (tid < 2 * VT) {
        if (tid < VT) {
            float s = 0.f;
#pragma unroll 6
            for (int u = 0; u < VT; u++) s += fabsf(incid[u * VT + tid]);
            dvv[tid] = wt[tid] / (s + 1e-8f);
        } else {
            int u = tid - VT;
            float s = 0.f;
#pragma unroll 6
            for (int v = 0; v < VT; v++) s += fabsf(incid[u * VT + v] * wt[v]);
            rss[u] = s + 1e-8f;
        }
    }
    __syncthreads();
    for (int e = tid; e < VT * VT; e += 128) tmp[e] = incid[e] * wt[e % VT] * dvv[e % VT];
    __syncthreads();

    float ra = fmaxf(alpha[0], 0.f);
    for (int e = tid; e < VT * VT; e += 128) {
        int u = e / VT, w = e % VT;
        const float* ru = tmp + u * VT;
        const float* rw = incid + w * VT;
        float ha = 0.f;
#pragma unroll 6
        for (int v = 0; v < VT; v++) ha += ru[v] * rw[v];
        ha /= rss[u];
        g_adj[(n * Kk + k) * (VT * VT) + e] = g_adjn[k * (VT * VT) + e] + ra * ha;
    }
}

// ---------------- kernel 3: fused conv + aggregate + BN + relu ----------------
__global__ __launch_bounds__(256, 4) void k_main(
    const float* __restrict__ x, const float* __restrict__ hj,
    const float* __restrict__ cdw, const float* __restrict__ cdb,
    const float* __restrict__ gam, const float* __restrict__ bet,
    float* __restrict__ out) {
    extern __shared__ float sm[];
    float* At = sm + AT_OFF;
    float* rowsA = sm + RA_OFF;
    float* Ws = sm + WS_OFF;
    float* XB = sm + XB_OFF;     // X [256x33] -> B [256x28] -> Y [32x200]

    int bid = blockIdx.x;
    int tb = bid & 7;
    int k = (bid >> 3) & 7;
    int n = bid >> 6;
    int tid = threadIdx.x;

    const float* gA = g_adj + (n * Kk + k) * (VT * VT);
    for (int e = tid; e < VT * BST; e += 256) {
        int v = e / BST, u = e - v * BST;
        At[e] = (u < Vv) ? gA[u * VT + v] : 0.f;
    }
    if (tid < BST) {
        float s = 0.f;
        if (tid < Vv) {
#pragma unroll
            for (int v = 0; v < VT; v++) s += gA[tid * VT + v];
        }
        rowsA[tid] = s;
    }
    for (int e = tid; e < CG * CG; e += 256) {
        int o = e >> 5, c = e & 31;
        Ws[o * 33 + c] = cdw[(k * OG + o) * CG + c];
    }
    {
        const float* gx = x + ((size_t)(n * Cc + k * CG) * Tt + tb * TB) * Vv;
        for (int e = tid; e < CG * TB * Vv; e += 256) {
            int c = e / (TB * Vv);
            int r = e - c * (TB * Vv);
            int tt = r / Vv;
            int v = r - tt * Vv;
            XB[(c * TB + tt) * XST + v] = gx[(size_t)c * (Tt * Vv) + r];
        }
        for (int e = tid; e < CG * TB * VNh; e += 256) {
            int c = e / (TB * VNh);
            int r = e - c * (TB * VNh);
            int tt = r / VNh;
            int j = r - tt * VNh;
            XB[(c * TB + tt) * XST + Vv + j] = hj[j * Cc + k * CG + c];
        }
    }
    __syncthreads();

    // --- stage B ---
    unsigned long long acc[14];
#pragma unroll
    for (int i = 0; i < 14; i++) acc[i] = 0ull;
    {
        const float* x0 = XB + tid * XST;
#pragma unroll 3
        for (int v = 0; v < VT; v++) {
            float xa = x0[v];
            unsigned long long xd = pack2(xa, xa);
            const ulonglong2* arow = (const ulonglong2*)(At + v * BST);
#pragma unroll
            for (int u4 = 0; u4 < 7; u4++) {
                ulonglong2 ap = arow[u4];
                fma2(acc[2 * u4], ap.x, xd);
                fma2(acc[2 * u4 + 1], ap.y, xd);
            }
        }
    }
    __syncthreads();
    {
        ulonglong2* b0 = (ulonglong2*)(XB + tid * BST);
#pragma unroll
        for (int u4 = 0; u4 < 7; u4++) {
            ulonglong2 s0;
            s0.x = acc[2 * u4];
            s0.y = acc[2 * u4 + 1];
            b0[u4] = s0;
        }
    }
    __syncthreads();

    // --- stage C: one (o, tt) per thread ---
    float y[26];
    {
        int ttl = tid & 7;
        int o = tid >> 3;
        int oo = k * OG + o;
        float bt = cdb[oo];
#pragma unroll
        for (int u2 = 0; u2 < 14; u2++)
            acc[u2] = pack2(bt * rowsA[2 * u2], bt * rowsA[2 * u2 + 1]);
#pragma unroll 4
        for (int c = 0; c < CG; c++) {
            float w = Ws[o * 33 + c];
            unsigned long long wd = pack2(w, w);
            const ulonglong2* bp = (const ulonglong2*)(XB + (c * TB + ttl) * BST);
#pragma unroll
            for (int u4 = 0; u4 < 7; u4++) {
                ulonglong2 bv = bp[u4];
                fma2(acc[2 * u4], wd, bv.x);
                fma2(acc[2 * u4 + 1], wd, bv.y);
            }
        }
        float scale = gam[oo] / sqrtf(1.0f + 1e-5f);
        float bb = bet[oo];
#pragma unroll
        for (int u2 = 0; u2 < 13; u2++) unpack2(acc[u2], y[2 * u2], y[2 * u2 + 1]);
#pragma unroll
        for (int u = 0; u < Vv; u++) y[u] = y[u] * scale + bb;
    }
    __syncthreads();   // all B reads done -> reuse XB for Y staging

    // stage Y into smem [o][ttl*25+u] (conflict-free scalar STS)
    {
        int ttl = tid & 7;
        int o = tid >> 3;
        float* yrow = XB + o * 200 + ttl * Vv;
#pragma unroll
        for (int u = 0; u < Vv; u++) yrow[u] = y[u];
    }
    __syncthreads();

    // coalesced epilogue: residual + relu + store, float4 throughout
    {
        size_t gbase4 = (((size_t)(n * Cc + k * OG) * Tt + tb * TB) * Vv) >> 2;
        const float4* xg = (const float4*)x + gbase4;
        float4* og = (float4*)out + gbase4;
        const float4* ys = (const float4*)XB;
        for (int e = tid; e < CG * 200 / 4; e += 256) {
            int o = e / 50;
            int r = e - o * 50;
            float4 xv = xg[o * (Tt * Vv / 4) + r];
            float4 yv = ys[e];
            float4 ov;
            ov.x = fmaxf(yv.x + xv.x, 0.f);
            ov.y = fmaxf(yv.y + xv.y, 0.f);
            ov.z = fmaxf(yv.z + xv.z, 0.f);
            ov.w = fmaxf(yv.w + xv.w, 0.f);
            og[o * (Tt * Vv / 4) + r] = ov;
        }
    }
}

// ---------------- launch ----------------
extern "C" void kernel_launch(void* const* d_in, const int* in_sizes, int n_in,
                              void* d_out, int out_size) {
    const float* x    = (const float*)d_in[0];
    const float* adjc = (const float*)d_in[1];
    const float* ei   = (const float*)d_in[2];
    const float* hj   = (const float*)d_in[3];
    const float* alp  = (const float*)d_in[4];
    const float* tvw  = (const float*)d_in[5];
    const float* tvb  = (const float*)d_in[6];
    const float* t1w  = (const float*)d_in[7];
    const float* t1b  = (const float*)d_in[8];
    const float* t2w  = (const float*)d_in[9];
    const float* t2b  = (const float*)d_in[10];
    const float* cdw  = (const float*)d_in[11];
    const float* cdb  = (const float*)d_in[12];
    const float* gam  = (const float*)d_in[13];
    const float* bet  = (const float*)d_in[14];
    float* out = (float*)d_out;

    int tail = out_size - Nn * OO * Tt * Vv;
    k_adjn<<<1, 256>>>(adjc, ei, hj, out, tail);
    k_pool<<<Nn * (Cc / 4), 256>>>(x, hj);
    k_hA<<<Nn * Kk, 128>>>(tvw, tvb, t1w, t1b);
    k_hB<<<Nn * Kk, 128>>>(t2w, t2b, alp);

    cudaFuncSetAttribute(k_main, cudaFuncAttributeMaxDynamicSharedMemorySize,
                         SM_TOTAL_FLOATS * 4);
    k_main<<<Nn * Kk * (Tt / TB), 256, SM_TOTAL_FLOATS * 4>>>(x, hj, cdw, cdb, gam, bet, out);
}